// round 11
// baseline (speedup 1.0000x reference)
#include <cuda_runtime.h>
#include <cstdint>

#define B_   512
#define M_   256
#define BM_  (B_*M_)      // 131072 rows
#define NGL  4

// Scratch (allocation-free rule: __device__ globals)
__device__ float g_Y[BM_*128];
__device__ float g_X[BM_*128];

// ---------------------------------------------------------------------------
// helpers
// ---------------------------------------------------------------------------
__device__ __forceinline__ uint32_t f2tf(float x) {
    uint32_t r;
    asm("cvt.rna.tf32.f32 %0, %1;" : "=r"(r) : "f"(x));
    return r;
}

__device__ __forceinline__ void mma8(float& c0, float& c1, float& c2, float& c3,
                                     uint32_t a0, uint32_t a1, uint32_t a2, uint32_t a3,
                                     uint32_t b0, uint32_t b1)
{
    asm volatile(
        "mma.sync.aligned.m16n8k8.row.col.f32.tf32.tf32.f32 "
        "{%0,%1,%2,%3}, {%4,%5,%6,%7}, {%8,%9}, {%0,%1,%2,%3};"
        : "+f"(c0), "+f"(c1), "+f"(c2), "+f"(c3)
        : "r"(a0), "r"(a1), "r"(a2), "r"(a3), "r"(b0), "r"(b1));
}

__device__ __forceinline__ uint32_t sptr(const void* p) {
    return (uint32_t)__cvta_generic_to_shared(p);
}
__device__ __forceinline__ void cp16(uint32_t s, const void* g) {
    asm volatile("cp.async.cg.shared.global [%0], [%1], 16;" :: "r"(s), "l"(g));
}
__device__ __forceinline__ void cp_commit() {
    asm volatile("cp.async.commit_group;");
}
template<int N> __device__ __forceinline__ void cp_wait() {
    asm volatile("cp.async.wait_group %0;" :: "n"(N));
}

// Chunk tiles: [128][ASTR] floats. ASTR=36 => conflict-free frag reads.
#define ASTR 36
// bmm B tile: [32][BSTR] floats (k-major). BSTR=136 => bank=(8t+g)%32.
#define BSTR 136

#define TILE_F   (128*ASTR)              // 4608 floats
#define STG_GEMM (TILE_F*2)
#define STG_BMM  (TILE_F + 32*BSTR)      // 8960 floats
#define DSMEM_GEMM  (STG_GEMM*2*4)       // 73728 B (2-stage)
#define DSMEM_BMM3  (STG_BMM*3*4)        // 107520 B (3-stage)

// ---------------------------------------------------------------------------
// warp-tile compute over one 32-k chunk (padded tiles), 64x32 warp tile.
// ---------------------------------------------------------------------------
template<bool BKM>
__device__ __forceinline__ void compute_chunk(const float* __restrict__ A_s,
                                              const float* __restrict__ B_s,
                                              int m0, int n0, int g, int t,
                                              float acc[4][4][4])
{
#pragma unroll
    for (int ks = 0; ks < 4; ks++) {
        const int k0 = ks * 8;
        uint32_t af[4][4];
#pragma unroll
        for (int i = 0; i < 4; i++) {
            int mr = m0 + 16 * i;
            af[i][0] = f2tf(A_s[(mr + g    ) * ASTR + k0 + t]);
            af[i][1] = f2tf(A_s[(mr + g + 8) * ASTR + k0 + t]);
            af[i][2] = f2tf(A_s[(mr + g    ) * ASTR + k0 + t + 4]);
            af[i][3] = f2tf(A_s[(mr + g + 8) * ASTR + k0 + t + 4]);
        }
        uint32_t bf[4][2];
#pragma unroll
        for (int j = 0; j < 4; j++) {
            int nb = n0 + 8 * j + g;
            if (BKM) {
                bf[j][0] = f2tf(B_s[(k0 + t    ) * BSTR + nb]);
                bf[j][1] = f2tf(B_s[(k0 + t + 4) * BSTR + nb]);
            } else {
                bf[j][0] = f2tf(B_s[nb * ASTR + k0 + t]);
                bf[j][1] = f2tf(B_s[nb * ASTR + k0 + t + 4]);
            }
        }
#pragma unroll
        for (int i = 0; i < 4; i++)
#pragma unroll
            for (int j = 0; j < 4; j++)
                mma8(acc[i][j][0], acc[i][j][1], acc[i][j][2], acc[i][j][3],
                     af[i][0], af[i][1], af[i][2], af[i][3],
                     bf[j][0], bf[j][1]);
    }
}

// ---------------------------------------------------------------------------
// gml layer GEMM: Y[r,n] = sum_k X[r,k]*W[n,k] + bias[n];  K=N=128.
// ---------------------------------------------------------------------------
__global__ __launch_bounds__(256, 2)
void gemm128_tc(const float* __restrict__ X, const float* __restrict__ W,
                const float* __restrict__ bias, float* __restrict__ Y)
{
    extern __shared__ float sm[];
    const int tid  = threadIdx.x;
    const int lane = tid & 31, wid = tid >> 5;
    const int g = lane >> 2, t = lane & 3;
    const int m0 = (wid >> 2) * 64;
    const int n0 = (wid & 3) * 32;
    const long row0 = (long)blockIdx.x * 128;

    auto fill = [&](int stage, int kc) {
        float* A_s = sm + stage * STG_GEMM;
        float* B_s = A_s + TILE_F;
#pragma unroll
        for (int it = 0; it < 4; it++) {
            int v = tid + it * 256;
            int rr = v >> 3, cc = (v & 7) * 4;
            cp16(sptr(&A_s[rr * ASTR + cc]), &X[(row0 + rr) * 128 + kc + cc]);
            cp16(sptr(&B_s[rr * ASTR + cc]), &W[rr * 128 + kc + cc]);
        }
    };

    float acc[4][4][4];
#pragma unroll
    for (int i = 0; i < 4; i++)
#pragma unroll
        for (int j = 0; j < 4; j++)
#pragma unroll
            for (int q = 0; q < 4; q++) acc[i][j][q] = 0.f;

    fill(0, 0); cp_commit();
#pragma unroll
    for (int c = 0; c < 4; c++) {
        if (c + 1 < 4) { fill((c + 1) & 1, (c + 1) * 32); cp_commit(); cp_wait<1>(); }
        else           { cp_wait<0>(); }
        __syncthreads();
        const float* A_s = sm + (c & 1) * STG_GEMM;
        compute_chunk<false>(A_s, A_s + TILE_F, m0, n0, g, t, acc);
        __syncthreads();
    }

#pragma unroll
    for (int j = 0; j < 4; j++) {
        int col = n0 + 8 * j + 2 * t;
        float bv0 = bias[col], bv1 = bias[col + 1];
#pragma unroll
        for (int i = 0; i < 4; i++) {
            long r0 = row0 + m0 + 16 * i + g;
            long r1 = r0 + 8;
            *(float2*)&Y[r0 * 128 + col] = make_float2(acc[i][j][0] + bv0,
                                                       acc[i][j][1] + bv1);
            *(float2*)&Y[r1 * 128 + col] = make_float2(acc[i][j][2] + bv0,
                                                       acc[i][j][3] + bv1);
        }
    }
}

// ---------------------------------------------------------------------------
// Xout[b,m,p] = relu( sum_n G0[b,m,n] * Yin[b,n,p] );  K=256, 3-stage ring.
// ---------------------------------------------------------------------------
__global__ __launch_bounds__(256, 2)
void bmm_relu_tc(const float* __restrict__ G, const float* __restrict__ Yin,
                 float* __restrict__ Xout)
{
    extern __shared__ float sm[];
    const int tid  = threadIdx.x;
    const int lane = tid & 31, wid = tid >> 5;
    const int g = lane >> 2, t = lane & 3;
    const int m0 = (wid >> 2) * 64;
    const int n0 = (wid & 3) * 32;
    const int b = blockIdx.y;
    const int row0 = blockIdx.x * 128;
    const float* A  = G   + (long)b * M_ * M_;
    const float* Bm = Yin + (long)b * M_ * 128;

    auto fill = [&](int stage, int kc) {
        float* A_s = sm + stage * STG_BMM;
        float* B_s = A_s + TILE_F;
#pragma unroll
        for (int it = 0; it < 4; it++) {
            int v = tid + it * 256;
            int rr = v >> 3, cc = (v & 7) * 4;
            cp16(sptr(&A_s[rr * ASTR + cc]), &A[(row0 + rr) * 256 + kc + cc]);
            int kk = v >> 5, nn = (v & 31) * 4;
            cp16(sptr(&B_s[kk * BSTR + nn]), &Bm[(kc + kk) * 128 + nn]);
        }
    };

    float acc[4][4][4];
#pragma unroll
    for (int i = 0; i < 4; i++)
#pragma unroll
        for (int j = 0; j < 4; j++)
#pragma unroll
            for (int q = 0; q < 4; q++) acc[i][j][q] = 0.f;

    fill(0, 0); cp_commit();
    fill(1, 32); cp_commit();
    for (int c = 0; c < 8; c++) {
        if (c + 2 < 8) { fill((c + 2) % 3, (c + 2) * 32); cp_commit(); cp_wait<2>(); }
        else if (c + 1 < 8) cp_wait<1>();
        else                cp_wait<0>();
        __syncthreads();
        const float* A_s = sm + (c % 3) * STG_BMM;
        compute_chunk<true>(A_s, A_s + TILE_F, m0, n0, g, t, acc);
        __syncthreads();
    }

    float* O = Xout + (long)b * M_ * 128;
#pragma unroll
    for (int j = 0; j < 4; j++) {
        int col = n0 + 8 * j + 2 * t;
#pragma unroll
        for (int i = 0; i < 4; i++) {
            int r0 = row0 + m0 + 16 * i + g;
            int r1 = r0 + 8;
            *(float2*)&O[r0 * 128 + col] =
                make_float2(fmaxf(acc[i][j][0], 0.f), fmaxf(acc[i][j][1], 0.f));
            *(float2*)&O[r1 * 128 + col] =
                make_float2(fmaxf(acc[i][j][2], 0.f), fmaxf(acc[i][j][3], 0.f));
        }
    }
}

// ===========================================================================
// Mega-fused trunk + head: 128-row blocks, 512 threads (16 warps, 32x32
// warp tiles, 4m x 4n). smem: H0,H1 swizzled 128x128 + 2 weight chunk
// buffers = 164 KB, 1 block/SM — occupancy via warps, not blocks.
// Stages: 0 lin0, 1 rin, {2,4,6} rb1_i (bias+relu), {3,5,7} rb2_i (+res),
//         8 rout, 9..16 head n-chunks. 68 chunk-slots.
// ===========================================================================
#define HTILE_F  (128*128)
#define WCHK_TF  TILE_F
#define DSMEM_TRUNK ((2*HTILE_F + 2*WCHK_TF)*4)   // 167936 B
#define NSTG 17
#define NSLOT (NSTG*4)

__global__ __launch_bounds__(512, 1)
void trunk_head_fused(const float* __restrict__ X,
    const float* __restrict__ lin0W, const float* __restrict__ lin0B,
    const float* __restrict__ rinW,  const float* __restrict__ rinB,
    const float* __restrict__ rb1W,  const float* __restrict__ rb1B,
    const float* __restrict__ rb2W,
    const float* __restrict__ routW, const float* __restrict__ routB,
    const float* __restrict__ f1W,   const float* __restrict__ f1B,
    const float* __restrict__ f2W,   const float* __restrict__ f2B,
    float* __restrict__ out)
{
    extern __shared__ float sm[];
    float* H0 = sm;                        // swizzled [128][128]
    float* H1 = sm + HTILE_F;
    float* Wc = sm + 2 * HTILE_F;          // 2 x [128][ASTR]

    const int tid  = threadIdx.x;
    const int lane = tid & 31, wid = tid >> 5;   // wid 0..15
    const int g = lane >> 2, t = lane & 3;
    const int m0 = (wid >> 2) * 32;        // 0,32,64,96 (warp tile 32x32)
    const int n0 = (wid & 3) * 32;
    const long row0 = (long)blockIdx.x * 128;

    const float* wp[NSTG];
    wp[0] = lin0W;  wp[1] = rinW;
    wp[2] = rb1W;            wp[3] = rb2W;
    wp[4] = rb1W + 16384;    wp[5] = rb2W + 16384;
    wp[6] = rb1W + 32768;    wp[7] = rb2W + 32768;
    wp[8] = routW;
#pragma unroll
    for (int i = 0; i < 8; i++) wp[9 + i] = f1W + (long)i * 16384;
    const float* bp[9] = { lin0B, rinB, rb1B, nullptr, rb1B + 128, nullptr,
                           rb1B + 256, nullptr, routB };

    auto fillWchunk = [&](int buf, int slot) {
        const float* Wp = wp[slot >> 2];
        int kc = (slot & 3) * 32;
        float* W_s = Wc + buf * WCHK_TF;
#pragma unroll
        for (int it = 0; it < 2; it++) {
            int v = tid + it * 512;
            int rr = v >> 3, cc = (v & 7) * 4;
            cp16(sptr(&W_s[rr * ASTR + cc]), &Wp[rr * 128 + kc + cc]);
        }
    };

    // prologue: X rows -> H0 (swizzled), weight chunk 0 -> buf 0
#pragma unroll
    for (int it = 0; it < 8; it++) {
        int v = tid + it * 512;
        int rr = v >> 5, cc = (v & 31) * 4;
        cp16(sptr(&H0[rr * 128 + (cc ^ ((rr & 7) << 2))]),
             &X[(row0 + rr) * 128 + cc]);
    }
    fillWchunk(0, 0);
    cp_commit(); cp_wait<0>(); __syncthreads();

    float psum[4];
#pragma unroll
    for (int q = 0; q < 4; q++) psum[q] = 0.f;

    float acc[2][4][4];

    for (int q = 0; q < NSLOT; q++) {
        const int s = q >> 2, c = q & 3;

        if (q + 1 < NSLOT) { fillWchunk((q + 1) & 1, q + 1); cp_commit(); }

        if (c == 0) {
#pragma unroll
            for (int i = 0; i < 2; i++)
#pragma unroll
                for (int j = 0; j < 4; j++)
#pragma unroll
                    for (int z = 0; z < 4; z++) acc[i][j][z] = 0.f;
        }

        const float* H_s = ((s & 1) || s >= 9) ? H1 : H0;
        const float* W_s = Wc + (q & 1) * WCHK_TF;
        const int kc = c * 32;
        const int sw = g << 2;
#pragma unroll
        for (int ks = 0; ks < 4; ks++) {
            const int k0 = ks * 8;
            uint32_t af[2][4];
#pragma unroll
            for (int i = 0; i < 2; i++) {
                int r0 = m0 + 16 * i + g;    // (r&7)==g
                int r1 = r0 + 8;
                af[i][0] = f2tf(H_s[r0 * 128 + ((kc + k0 + t    ) ^ sw)]);
                af[i][1] = f2tf(H_s[r1 * 128 + ((kc + k0 + t    ) ^ sw)]);
                af[i][2] = f2tf(H_s[r0 * 128 + ((kc + k0 + t + 4) ^ sw)]);
                af[i][3] = f2tf(H_s[r1 * 128 + ((kc + k0 + t + 4) ^ sw)]);
            }
            uint32_t bf[4][2];
#pragma unroll
            for (int j = 0; j < 4; j++) {
                int nb = n0 + 8 * j + g;
                bf[j][0] = f2tf(W_s[nb * ASTR + k0 + t]);
                bf[j][1] = f2tf(W_s[nb * ASTR + k0 + t + 4]);
            }
#pragma unroll
            for (int i = 0; i < 2; i++)
#pragma unroll
                for (int j = 0; j < 4; j++)
                    mma8(acc[i][j][0], acc[i][j][1], acc[i][j][2], acc[i][j][3],
                         af[i][0], af[i][1], af[i][2], af[i][3],
                         bf[j][0], bf[j][1]);
        }

        if (c == 3) {
            if (s < 9) {
                float* D = (s & 1) ? H0 : H1;
                const bool relu = (s == 2 || s == 4 || s == 6);
                const bool res  = (s == 3 || s == 5 || s == 7);
                const float* bias = bp[s];
#pragma unroll
                for (int j = 0; j < 4; j++) {
                    int col = n0 + 8 * j + 2 * t;
                    float bv0 = bias ? bias[col]     : 0.f;
                    float bv1 = bias ? bias[col + 1] : 0.f;
#pragma unroll
                    for (int i = 0; i < 2; i++) {
                        int r0 = m0 + 16 * i + g;   // (r&7)==g
                        int r1 = r0 + 8;
                        int p0 = r0 * 128 + (col ^ sw);
                        int p1 = r1 * 128 + (col ^ sw);
                        float v00 = acc[i][j][0] + bv0, v01 = acc[i][j][1] + bv1;
                        float v10 = acc[i][j][2] + bv0, v11 = acc[i][j][3] + bv1;
                        if (relu) { v00 = fmaxf(v00, 0.f); v01 = fmaxf(v01, 0.f);
                                    v10 = fmaxf(v10, 0.f); v11 = fmaxf(v11, 0.f); }
                        if (res) {
                            float2 e0 = *(const float2*)&D[p0];
                            float2 e1 = *(const float2*)&D[p1];
                            v00 += e0.x; v01 += e0.y; v10 += e1.x; v11 += e1.y;
                        }
                        *(float2*)&D[p0] = make_float2(v00, v01);
                        *(float2*)&D[p1] = make_float2(v10, v11);
                    }
                }
            } else {
                int ncb = (s - 9) * 128;
#pragma unroll
                for (int j = 0; j < 4; j++) {
                    int col = ncb + n0 + 8 * j + 2 * t;
                    float bb0 = f1B[col], bb1 = f1B[col + 1];
                    float s0  = f2W[col], s1  = f2W[col + 1];
#pragma unroll
                    for (int i = 0; i < 2; i++) {
                        psum[2*i]   += fmaxf(acc[i][j][0] + bb0, 0.f) * s0
                                     + fmaxf(acc[i][j][1] + bb1, 0.f) * s1;
                        psum[2*i+1] += fmaxf(acc[i][j][2] + bb0, 0.f) * s0
                                     + fmaxf(acc[i][j][3] + bb1, 0.f) * s1;
                    }
                }
            }
        }

        if (q + 1 < NSLOT) cp_wait<0>();
        __syncthreads();
    }

    // reduce 16 partials per row (4 n-warps x 4 t); overlay scratch on Wc
    float (*red)[17] = (float(*)[17])Wc;
    const int qn = (wid & 3) * 4 + t;
#pragma unroll
    for (int i = 0; i < 2; i++) {
        red[m0 + 16 * i + g    ][qn] = psum[2*i];
        red[m0 + 16 * i + g + 8][qn] = psum[2*i+1];
    }
    __syncthreads();
    if (tid < 128) {
        float sum = f2B[0];
#pragma unroll
        for (int k = 0; k < 16; k++) sum += red[tid][k];
        out[row0 + tid] = sum;
    }
}

// ---------------------------------------------------------------------------
extern "C" void kernel_launch(void* const* d_in, const int* in_sizes, int n_in,
                              void* d_out, int out_size)
{
    const float* G     = (const float*)d_in[0];
    const float* xG    = (const float*)d_in[1];
    const float* gmlW  = (const float*)d_in[2];
    const float* gmlB  = (const float*)d_in[3];
    const float* lin0W = (const float*)d_in[4];
    const float* lin0B = (const float*)d_in[5];
    const float* rinW  = (const float*)d_in[6];
    const float* rinB  = (const float*)d_in[7];
    const float* rb1W  = (const float*)d_in[8];
    const float* rb1B  = (const float*)d_in[9];
    const float* rb2W  = (const float*)d_in[10];
    const float* routW = (const float*)d_in[11];
    const float* routB = (const float*)d_in[12];
    const float* f1W   = (const float*)d_in[13];
    const float* f1B   = (const float*)d_in[14];
    const float* f2W   = (const float*)d_in[15];
    const float* f2B   = (const float*)d_in[16];
    float* out = (float*)d_out;

    float *bY, *bX;
    cudaGetSymbolAddress((void**)&bY, g_Y);
    cudaGetSymbolAddress((void**)&bX, g_X);

    cudaFuncSetAttribute(gemm128_tc,
                         cudaFuncAttributeMaxDynamicSharedMemorySize, DSMEM_GEMM);
    cudaFuncSetAttribute(bmm_relu_tc,
                         cudaFuncAttributeMaxDynamicSharedMemorySize, DSMEM_BMM3);
    cudaFuncSetAttribute(trunk_head_fused,
                         cudaFuncAttributeMaxDynamicSharedMemorySize, DSMEM_TRUNK);

    const int GB = BM_ / 128;   // 1024 blocks
    dim3 blk(256);

    // GNN message-passing layers (split kernels — R8-proven)
    const float* xcur = xG;
    for (int l = 0; l < NGL; l++) {
        gemm128_tc<<<GB, blk, DSMEM_GEMM>>>(xcur, gmlW + (long)l * 16384,
                                            gmlB + l * 128, bY);
        bmm_relu_tc<<<dim3(2, B_), blk, DSMEM_BMM3>>>(G, bY, bX);
        xcur = bX;
    }

    // Fused MLP trunk + head (128-row blocks, 512 threads / 16 warps)
    trunk_head_fused<<<GB, 512, DSMEM_TRUNK>>>(bX,
        lin0W, lin0B, rinW, rinB, rb1W, rb1B, rb2W, routW, routB,
        f1W, f1B, f2W, f2B, out);
}

// round 12
// speedup vs baseline: 1.0868x; 1.0868x over previous
#include <cuda_runtime.h>
#include <cstdint>

#define B_   512
#define M_   256
#define BM_  (B_*M_)      // 131072 rows
#define NGL  4

// Scratch (allocation-free rule: __device__ globals)
__device__ float g_Y[BM_*128];
__device__ float g_X[BM_*128];

// ---------------------------------------------------------------------------
// helpers
// ---------------------------------------------------------------------------
__device__ __forceinline__ uint32_t f2tf(float x) {
    uint32_t r;
    asm("cvt.rna.tf32.f32 %0, %1;" : "=r"(r) : "f"(x));
    return r;
}

__device__ __forceinline__ void mma8(float& c0, float& c1, float& c2, float& c3,
                                     uint32_t a0, uint32_t a1, uint32_t a2, uint32_t a3,
                                     uint32_t b0, uint32_t b1)
{
    asm volatile(
        "mma.sync.aligned.m16n8k8.row.col.f32.tf32.tf32.f32 "
        "{%0,%1,%2,%3}, {%4,%5,%6,%7}, {%8,%9}, {%0,%1,%2,%3};"
        : "+f"(c0), "+f"(c1), "+f"(c2), "+f"(c3)
        : "r"(a0), "r"(a1), "r"(a2), "r"(a3), "r"(b0), "r"(b1));
}

__device__ __forceinline__ uint32_t sptr(const void* p) {
    return (uint32_t)__cvta_generic_to_shared(p);
}
__device__ __forceinline__ void cp16(uint32_t s, const void* g) {
    asm volatile("cp.async.cg.shared.global [%0], [%1], 16;" :: "r"(s), "l"(g));
}
__device__ __forceinline__ void cp_commit() {
    asm volatile("cp.async.commit_group;");
}
template<int N> __device__ __forceinline__ void cp_wait() {
    asm volatile("cp.async.wait_group %0;" :: "n"(N));
}

// Chunk tiles: [128][ASTR] floats. ASTR=36 => conflict-free frag reads.
#define ASTR 36
// bmm B tile: [32][BSTR] floats (k-major). BSTR=136 => bank=(8t+g)%32.
#define BSTR 136

#define TILE_F   (128*ASTR)              // 4608 floats
#define STG_GEMM (TILE_F*2)
#define STG_BMM  (TILE_F + 32*BSTR)      // 8960 floats
#define DSMEM_GEMM  (STG_GEMM*2*4)       // 73728 B (2-stage)
#define DSMEM_BMM3  (STG_BMM*3*4)        // 107520 B (3-stage)

// ---------------------------------------------------------------------------
// warp-tile compute over one 32-k chunk (padded tiles), 64x32 warp tile.
// (used by gemm128 and bmm — unchanged, R8-proven)
// ---------------------------------------------------------------------------
template<bool BKM>
__device__ __forceinline__ void compute_chunk(const float* __restrict__ A_s,
                                              const float* __restrict__ B_s,
                                              int m0, int n0, int g, int t,
                                              float acc[4][4][4])
{
#pragma unroll
    for (int ks = 0; ks < 4; ks++) {
        const int k0 = ks * 8;
        uint32_t af[4][4];
#pragma unroll
        for (int i = 0; i < 4; i++) {
            int mr = m0 + 16 * i;
            af[i][0] = f2tf(A_s[(mr + g    ) * ASTR + k0 + t]);
            af[i][1] = f2tf(A_s[(mr + g + 8) * ASTR + k0 + t]);
            af[i][2] = f2tf(A_s[(mr + g    ) * ASTR + k0 + t + 4]);
            af[i][3] = f2tf(A_s[(mr + g + 8) * ASTR + k0 + t + 4]);
        }
        uint32_t bf[4][2];
#pragma unroll
        for (int j = 0; j < 4; j++) {
            int nb = n0 + 8 * j + g;
            if (BKM) {
                bf[j][0] = f2tf(B_s[(k0 + t    ) * BSTR + nb]);
                bf[j][1] = f2tf(B_s[(k0 + t + 4) * BSTR + nb]);
            } else {
                bf[j][0] = f2tf(B_s[nb * ASTR + k0 + t]);
                bf[j][1] = f2tf(B_s[nb * ASTR + k0 + t + 4]);
            }
        }
#pragma unroll
        for (int i = 0; i < 4; i++)
#pragma unroll
            for (int j = 0; j < 4; j++)
                mma8(acc[i][j][0], acc[i][j][1], acc[i][j][2], acc[i][j][3],
                     af[i][0], af[i][1], af[i][2], af[i][3],
                     bf[j][0], bf[j][1]);
    }
}

// ---------------------------------------------------------------------------
// gml layer GEMM: Y[r,n] = sum_k X[r,k]*W[n,k] + bias[n];  K=N=128.
// ---------------------------------------------------------------------------
__global__ __launch_bounds__(256, 2)
void gemm128_tc(const float* __restrict__ X, const float* __restrict__ W,
                const float* __restrict__ bias, float* __restrict__ Y)
{
    extern __shared__ float sm[];
    const int tid  = threadIdx.x;
    const int lane = tid & 31, wid = tid >> 5;
    const int g = lane >> 2, t = lane & 3;
    const int m0 = (wid >> 2) * 64;
    const int n0 = (wid & 3) * 32;
    const long row0 = (long)blockIdx.x * 128;

    auto fill = [&](int stage, int kc) {
        float* A_s = sm + stage * STG_GEMM;
        float* B_s = A_s + TILE_F;
#pragma unroll
        for (int it = 0; it < 4; it++) {
            int v = tid + it * 256;
            int rr = v >> 3, cc = (v & 7) * 4;
            cp16(sptr(&A_s[rr * ASTR + cc]), &X[(row0 + rr) * 128 + kc + cc]);
            cp16(sptr(&B_s[rr * ASTR + cc]), &W[rr * 128 + kc + cc]);
        }
    };

    float acc[4][4][4];
#pragma unroll
    for (int i = 0; i < 4; i++)
#pragma unroll
        for (int j = 0; j < 4; j++)
#pragma unroll
            for (int q = 0; q < 4; q++) acc[i][j][q] = 0.f;

    fill(0, 0); cp_commit();
#pragma unroll
    for (int c = 0; c < 4; c++) {
        if (c + 1 < 4) { fill((c + 1) & 1, (c + 1) * 32); cp_commit(); cp_wait<1>(); }
        else           { cp_wait<0>(); }
        __syncthreads();
        const float* A_s = sm + (c & 1) * STG_GEMM;
        compute_chunk<false>(A_s, A_s + TILE_F, m0, n0, g, t, acc);
        __syncthreads();
    }

#pragma unroll
    for (int j = 0; j < 4; j++) {
        int col = n0 + 8 * j + 2 * t;
        float bv0 = bias[col], bv1 = bias[col + 1];
#pragma unroll
        for (int i = 0; i < 4; i++) {
            long r0 = row0 + m0 + 16 * i + g;
            long r1 = r0 + 8;
            *(float2*)&Y[r0 * 128 + col] = make_float2(acc[i][j][0] + bv0,
                                                       acc[i][j][1] + bv1);
            *(float2*)&Y[r1 * 128 + col] = make_float2(acc[i][j][2] + bv0,
                                                       acc[i][j][3] + bv1);
        }
    }
}

// ---------------------------------------------------------------------------
// Xout[b,m,p] = relu( sum_n G0[b,m,n] * Yin[b,n,p] );  K=256, 3-stage ring.
// ---------------------------------------------------------------------------
__global__ __launch_bounds__(256, 2)
void bmm_relu_tc(const float* __restrict__ G, const float* __restrict__ Yin,
                 float* __restrict__ Xout)
{
    extern __shared__ float sm[];
    const int tid  = threadIdx.x;
    const int lane = tid & 31, wid = tid >> 5;
    const int g = lane >> 2, t = lane & 3;
    const int m0 = (wid >> 2) * 64;
    const int n0 = (wid & 3) * 32;
    const int b = blockIdx.y;
    const int row0 = blockIdx.x * 128;
    const float* A  = G   + (long)b * M_ * M_;
    const float* Bm = Yin + (long)b * M_ * 128;

    auto fill = [&](int stage, int kc) {
        float* A_s = sm + stage * STG_BMM;
        float* B_s = A_s + TILE_F;
#pragma unroll
        for (int it = 0; it < 4; it++) {
            int v = tid + it * 256;
            int rr = v >> 3, cc = (v & 7) * 4;
            cp16(sptr(&A_s[rr * ASTR + cc]), &A[(row0 + rr) * 256 + kc + cc]);
            int kk = v >> 5, nn = (v & 31) * 4;
            cp16(sptr(&B_s[kk * BSTR + nn]), &Bm[(kc + kk) * 128 + nn]);
        }
    };

    float acc[4][4][4];
#pragma unroll
    for (int i = 0; i < 4; i++)
#pragma unroll
        for (int j = 0; j < 4; j++)
#pragma unroll
            for (int q = 0; q < 4; q++) acc[i][j][q] = 0.f;

    fill(0, 0); cp_commit();
    fill(1, 32); cp_commit();
    for (int c = 0; c < 8; c++) {
        if (c + 2 < 8) { fill((c + 2) % 3, (c + 2) * 32); cp_commit(); cp_wait<2>(); }
        else if (c + 1 < 8) cp_wait<1>();
        else                cp_wait<0>();
        __syncthreads();
        const float* A_s = sm + (c % 3) * STG_BMM;
        compute_chunk<true>(A_s, A_s + TILE_F, m0, n0, g, t, acc);
        __syncthreads();
    }

    float* O = Xout + (long)b * M_ * 128;
#pragma unroll
    for (int j = 0; j < 4; j++) {
        int col = n0 + 8 * j + 2 * t;
#pragma unroll
        for (int i = 0; i < 4; i++) {
            int r0 = row0 + m0 + 16 * i + g;
            int r1 = r0 + 8;
            *(float2*)&O[r0 * 128 + col] =
                make_float2(fmaxf(acc[i][j][0], 0.f), fmaxf(acc[i][j][1], 0.f));
            *(float2*)&O[r1 * 128 + col] =
                make_float2(fmaxf(acc[i][j][2], 0.f), fmaxf(acc[i][j][3], 0.f));
        }
    }
}

// ===========================================================================
// Mega-fused trunk + head — R8 shape (128-row blocks, 256 threads, 64x32
// warp tiles, 1 block/SM) + software-pipelined fragment loads: ks+1's
// fragments are loaded into a second register buffer while ks's MMAs issue.
// Stages: 0 lin0, 1 rin, {2,4,6} rb1_i (bias+relu), {3,5,7} rb2_i (+res),
//         8 rout, 9..16 head n-chunks. 68 chunk-slots.
// ===========================================================================
#define HTILE_F  (128*128)
#define WCHK_TF  TILE_F
#define DSMEM_TRUNK ((2*HTILE_F + 2*WCHK_TF)*4)   // 167936 B
#define NSTG 17
#define NSLOT (NSTG*4)

__global__ __launch_bounds__(256, 1)
void trunk_head_fused(const float* __restrict__ X,
    const float* __restrict__ lin0W, const float* __restrict__ lin0B,
    const float* __restrict__ rinW,  const float* __restrict__ rinB,
    const float* __restrict__ rb1W,  const float* __restrict__ rb1B,
    const float* __restrict__ rb2W,
    const float* __restrict__ routW, const float* __restrict__ routB,
    const float* __restrict__ f1W,   const float* __restrict__ f1B,
    const float* __restrict__ f2W,   const float* __restrict__ f2B,
    float* __restrict__ out)
{
    extern __shared__ float sm[];
    float* H0 = sm;                        // swizzled [128][128]
    float* H1 = sm + HTILE_F;
    float* Wc = sm + 2 * HTILE_F;          // 2 x [128][ASTR]

    const int tid  = threadIdx.x;
    const int lane = tid & 31, wid = tid >> 5;
    const int g = lane >> 2, t = lane & 3;
    const int m0 = (wid >> 2) * 64;
    const int n0 = (wid & 3) * 32;
    const long row0 = (long)blockIdx.x * 128;
    const int sw = g << 2;

    const float* wp[NSTG];
    wp[0] = lin0W;  wp[1] = rinW;
    wp[2] = rb1W;            wp[3] = rb2W;
    wp[4] = rb1W + 16384;    wp[5] = rb2W + 16384;
    wp[6] = rb1W + 32768;    wp[7] = rb2W + 32768;
    wp[8] = routW;
#pragma unroll
    for (int i = 0; i < 8; i++) wp[9 + i] = f1W + (long)i * 16384;
    const float* bp[9] = { lin0B, rinB, rb1B, nullptr, rb1B + 128, nullptr,
                           rb1B + 256, nullptr, routB };

    auto fillWchunk = [&](int buf, int slot) {
        const float* Wp = wp[slot >> 2];
        int kc = (slot & 3) * 32;
        float* W_s = Wc + buf * WCHK_TF;
#pragma unroll
        for (int it = 0; it < 4; it++) {
            int v = tid + it * 256;
            int rr = v >> 3, cc = (v & 7) * 4;
            cp16(sptr(&W_s[rr * ASTR + cc]), &Wp[rr * 128 + kc + cc]);
        }
    };

    // prologue: X rows -> H0 (swizzled), weight chunk 0 -> buf 0
#pragma unroll
    for (int it = 0; it < 16; it++) {
        int v = tid + it * 256;
        int rr = v >> 5, cc = (v & 31) * 4;
        cp16(sptr(&H0[rr * 128 + (cc ^ ((rr & 7) << 2))]),
             &X[(row0 + rr) * 128 + cc]);
    }
    fillWchunk(0, 0);
    cp_commit(); cp_wait<0>(); __syncthreads();

    float psum[8];
#pragma unroll
    for (int q = 0; q < 8; q++) psum[q] = 0.f;

    float acc[4][4][4];

    for (int q = 0; q < NSLOT; q++) {
        const int s = q >> 2, c = q & 3;

        if (q + 1 < NSLOT) { fillWchunk((q + 1) & 1, q + 1); cp_commit(); }

        if (c == 0) {
#pragma unroll
            for (int i = 0; i < 4; i++)
#pragma unroll
                for (int j = 0; j < 4; j++)
#pragma unroll
                    for (int z = 0; z < 4; z++) acc[i][j][z] = 0.f;
        }

        const float* H_s = ((s & 1) || s >= 9) ? H1 : H0;
        const float* W_s = Wc + (q & 1) * WCHK_TF;
        const int kc = c * 32;

        // ---- software-pipelined fragment loads across the 4 ks steps ----
        auto loadFrag = [&](int k0, uint32_t af[4][4], uint32_t bf[4][2]) {
#pragma unroll
            for (int i = 0; i < 4; i++) {
                int r0 = m0 + 16 * i + g;    // (r&7)==g
                int r1 = r0 + 8;
                af[i][0] = f2tf(H_s[r0 * 128 + ((kc + k0 + t    ) ^ sw)]);
                af[i][1] = f2tf(H_s[r1 * 128 + ((kc + k0 + t    ) ^ sw)]);
                af[i][2] = f2tf(H_s[r0 * 128 + ((kc + k0 + t + 4) ^ sw)]);
                af[i][3] = f2tf(H_s[r1 * 128 + ((kc + k0 + t + 4) ^ sw)]);
            }
#pragma unroll
            for (int j = 0; j < 4; j++) {
                int nb = n0 + 8 * j + g;
                bf[j][0] = f2tf(W_s[nb * ASTR + k0 + t]);
                bf[j][1] = f2tf(W_s[nb * ASTR + k0 + t + 4]);
            }
        };
        auto doMMA = [&](uint32_t af[4][4], uint32_t bf[4][2]) {
#pragma unroll
            for (int i = 0; i < 4; i++)
#pragma unroll
                for (int j = 0; j < 4; j++)
                    mma8(acc[i][j][0], acc[i][j][1], acc[i][j][2], acc[i][j][3],
                         af[i][0], af[i][1], af[i][2], af[i][3],
                         bf[j][0], bf[j][1]);
        };

        uint32_t afA[4][4], bfA[4][2], afB[4][4], bfB[4][2];
        loadFrag(0, afA, bfA);
        loadFrag(8, afB, bfB);   doMMA(afA, bfA);
        loadFrag(16, afA, bfA);  doMMA(afB, bfB);
        loadFrag(24, afB, bfB);  doMMA(afA, bfA);
        doMMA(afB, bfB);

        if (c == 3) {
            if (s < 9) {
                float* D = (s & 1) ? H0 : H1;
                const bool relu = (s == 2 || s == 4 || s == 6);
                const bool res  = (s == 3 || s == 5 || s == 7);
                const float* bias = bp[s];
#pragma unroll
                for (int j = 0; j < 4; j++) {
                    int col = n0 + 8 * j + 2 * t;
                    float bv0 = bias ? bias[col]     : 0.f;
                    float bv1 = bias ? bias[col + 1] : 0.f;
#pragma unroll
                    for (int i = 0; i < 4; i++) {
                        int r0 = m0 + 16 * i + g;   // (r&7)==g
                        int r1 = r0 + 8;
                        int p0 = r0 * 128 + (col ^ sw);
                        int p1 = r1 * 128 + (col ^ sw);
                        float v00 = acc[i][j][0] + bv0, v01 = acc[i][j][1] + bv1;
                        float v10 = acc[i][j][2] + bv0, v11 = acc[i][j][3] + bv1;
                        if (relu) { v00 = fmaxf(v00, 0.f); v01 = fmaxf(v01, 0.f);
                                    v10 = fmaxf(v10, 0.f); v11 = fmaxf(v11, 0.f); }
                        if (res) {
                            float2 e0 = *(const float2*)&D[p0];
                            float2 e1 = *(const float2*)&D[p1];
                            v00 += e0.x; v01 += e0.y; v10 += e1.x; v11 += e1.y;
                        }
                        *(float2*)&D[p0] = make_float2(v00, v01);
                        *(float2*)&D[p1] = make_float2(v10, v11);
                    }
                }
            } else {
                int ncb = (s - 9) * 128;
#pragma unroll
                for (int j = 0; j < 4; j++) {
                    int col = ncb + n0 + 8 * j + 2 * t;
                    float bb0 = f1B[col], bb1 = f1B[col + 1];
                    float s0  = f2W[col], s1  = f2W[col + 1];
#pragma unroll
                    for (int i = 0; i < 4; i++) {
                        psum[2*i]   += fmaxf(acc[i][j][0] + bb0, 0.f) * s0
                                     + fmaxf(acc[i][j][1] + bb1, 0.f) * s1;
                        psum[2*i+1] += fmaxf(acc[i][j][2] + bb0, 0.f) * s0
                                     + fmaxf(acc[i][j][3] + bb1, 0.f) * s1;
                    }
                }
            }
        }

        if (q + 1 < NSLOT) cp_wait<0>();
        __syncthreads();
    }

    // reduce 16 partials per row; overlay scratch on weight buffers
    float (*red)[17] = (float(*)[17])Wc;
    const int qn = (wid & 3) * 4 + t;
#pragma unroll
    for (int i = 0; i < 4; i++) {
        red[m0 + 16 * i + g    ][qn] = psum[2*i];
        red[m0 + 16 * i + g + 8][qn] = psum[2*i+1];
    }
    __syncthreads();
    if (tid < 128) {
        float sum = f2B[0];
#pragma unroll
        for (int k = 0; k < 16; k++) sum += red[tid][k];
        out[row0 + tid] = sum;
    }
}

// ---------------------------------------------------------------------------
extern "C" void kernel_launch(void* const* d_in, const int* in_sizes, int n_in,
                              void* d_out, int out_size)
{
    const float* G     = (const float*)d_in[0];
    const float* xG    = (const float*)d_in[1];
    const float* gmlW  = (const float*)d_in[2];
    const float* gmlB  = (const float*)d_in[3];
    const float* lin0W = (const float*)d_in[4];
    const float* lin0B = (const float*)d_in[5];
    const float* rinW  = (const float*)d_in[6];
    const float* rinB  = (const float*)d_in[7];
    const float* rb1W  = (const float*)d_in[8];
    const float* rb1B  = (const float*)d_in[9];
    const float* rb2W  = (const float*)d_in[10];
    const float* routW = (const float*)d_in[11];
    const float* routB = (const float*)d_in[12];
    const float* f1W   = (const float*)d_in[13];
    const float* f1B   = (const float*)d_in[14];
    const float* f2W   = (const float*)d_in[15];
    const float* f2B   = (const float*)d_in[16];
    float* out = (float*)d_out;

    float *bY, *bX;
    cudaGetSymbolAddress((void**)&bY, g_Y);
    cudaGetSymbolAddress((void**)&bX, g_X);

    cudaFuncSetAttribute(gemm128_tc,
                         cudaFuncAttributeMaxDynamicSharedMemorySize, DSMEM_GEMM);
    cudaFuncSetAttribute(bmm_relu_tc,
                         cudaFuncAttributeMaxDynamicSharedMemorySize, DSMEM_BMM3);
    cudaFuncSetAttribute(trunk_head_fused,
                         cudaFuncAttributeMaxDynamicSharedMemorySize, DSMEM_TRUNK);

    const int GB = BM_ / 128;   // 1024 blocks
    dim3 blk(256);

    // GNN message-passing layers (split kernels — R8-proven)
    const float* xcur = xG;
    for (int l = 0; l < NGL; l++) {
        gemm128_tc<<<GB, blk, DSMEM_GEMM>>>(xcur, gmlW + (long)l * 16384,
                                            gmlB + l * 128, bY);
        bmm_relu_tc<<<dim3(2, B_), blk, DSMEM_BMM3>>>(G, bY, bX);
        xcur = bX;
    }

    // Fused MLP trunk + head (R8 shape + pipelined fragment loads)
    trunk_head_fused<<<GB, blk, DSMEM_TRUNK>>>(bX,
        lin0W, lin0B, rinW, rinB, rb1W, rb1B, rb2W, routW, routB,
        f1W, f1B, f2W, f2B, out);
}

// round 13
// speedup vs baseline: 1.1927x; 1.0974x over previous
#include <cuda_runtime.h>
#include <cstdint>

#define B_   512
#define M_   256
#define BM_  (B_*M_)      // 131072 rows
#define NGL  4

// Scratch (allocation-free rule: __device__ globals)
__device__ float g_Y[BM_*128];
__device__ float g_X[BM_*128];
// pre-converted tf32 weight bits: gml stages 0..3, then trunk stages 0..16
#define NWT (21*16384)
__device__ uint32_t g_Wt[NWT];

// ---------------------------------------------------------------------------
// helpers
// ---------------------------------------------------------------------------
__device__ __forceinline__ uint32_t f2tf(float x) {
    uint32_t r;
    asm("cvt.rna.tf32.f32 %0, %1;" : "=r"(r) : "f"(x));
    return r;
}

__device__ __forceinline__ void mma8(float& c0, float& c1, float& c2, float& c3,
                                     uint32_t a0, uint32_t a1, uint32_t a2, uint32_t a3,
                                     uint32_t b0, uint32_t b1)
{
    asm volatile(
        "mma.sync.aligned.m16n8k8.row.col.f32.tf32.tf32.f32 "
        "{%0,%1,%2,%3}, {%4,%5,%6,%7}, {%8,%9}, {%0,%1,%2,%3};"
        : "+f"(c0), "+f"(c1), "+f"(c2), "+f"(c3)
        : "r"(a0), "r"(a1), "r"(a2), "r"(a3), "r"(b0), "r"(b1));
}

__device__ __forceinline__ uint32_t sptr(const void* p) {
    return (uint32_t)__cvta_generic_to_shared(p);
}
__device__ __forceinline__ void cp16(uint32_t s, const void* g) {
    asm volatile("cp.async.cg.shared.global [%0], [%1], 16;" :: "r"(s), "l"(g));
}
__device__ __forceinline__ void cp_commit() {
    asm volatile("cp.async.commit_group;");
}
template<int N> __device__ __forceinline__ void cp_wait() {
    asm volatile("cp.async.wait_group %0;" :: "n"(N));
}

#define ASTR 36
#define BSTR 136
#define TILE_F   (128*ASTR)
#define STG_GEMM (TILE_F*2)
#define STG_BMM  (TILE_F + 32*BSTR)
#define DSMEM_GEMM  (STG_GEMM*2*4)
#define DSMEM_BMM3  (STG_BMM*3*4)

// ---------------------------------------------------------------------------
// weight pre-convert: fp32 -> tf32 bits (once per launch, bit-identical to
// what downstream cvt.rna would produce)
// ---------------------------------------------------------------------------
__global__ void convert_weights(const float* __restrict__ gmlW,
                                const float* __restrict__ lin0W,
                                const float* __restrict__ rinW,
                                const float* __restrict__ rb1W,
                                const float* __restrict__ rb2W,
                                const float* __restrict__ routW,
                                const float* __restrict__ f1W)
{
    int idx = blockIdx.x * 256 + threadIdx.x;
    if (idx >= NWT) return;
    float v;
    if (idx < 4 * 16384) {
        v = gmlW[idx];
    } else {
        int j = idx - 4 * 16384;
        int s = j >> 14, off = j & 16383;
        switch (s) {
            case 0: v = lin0W[off]; break;
            case 1: v = rinW[off]; break;
            case 2: v = rb1W[off]; break;
            case 3: v = rb2W[off]; break;
            case 4: v = rb1W[16384 + off]; break;
            case 5: v = rb2W[16384 + off]; break;
            case 6: v = rb1W[32768 + off]; break;
            case 7: v = rb2W[32768 + off]; break;
            case 8: v = routW[off]; break;
            default: v = f1W[(s - 9) * 16384 + off]; break;
        }
    }
    g_Wt[idx] = f2tf(v);
}

// ---------------------------------------------------------------------------
// warp-tile compute over one 32-k chunk. ACVT: apply cvt to A-side (fp32 in
// smem); B-side is always raw tf32 bits.
// ---------------------------------------------------------------------------
template<bool BKM, bool ACVT>
__device__ __forceinline__ void compute_chunk(const float* __restrict__ A_s,
                                              const float* __restrict__ B_s,
                                              int m0, int n0, int g, int t,
                                              float acc[4][4][4])
{
    const uint32_t* Au = (const uint32_t*)A_s;
    const uint32_t* Bu = (const uint32_t*)B_s;
#pragma unroll
    for (int ks = 0; ks < 4; ks++) {
        const int k0 = ks * 8;
        uint32_t af[4][4];
#pragma unroll
        for (int i = 0; i < 4; i++) {
            int mr = m0 + 16 * i;
            if (ACVT) {
                af[i][0] = f2tf(A_s[(mr + g    ) * ASTR + k0 + t]);
                af[i][1] = f2tf(A_s[(mr + g + 8) * ASTR + k0 + t]);
                af[i][2] = f2tf(A_s[(mr + g    ) * ASTR + k0 + t + 4]);
                af[i][3] = f2tf(A_s[(mr + g + 8) * ASTR + k0 + t + 4]);
            } else {
                af[i][0] = Au[(mr + g    ) * ASTR + k0 + t];
                af[i][1] = Au[(mr + g + 8) * ASTR + k0 + t];
                af[i][2] = Au[(mr + g    ) * ASTR + k0 + t + 4];
                af[i][3] = Au[(mr + g + 8) * ASTR + k0 + t + 4];
            }
        }
        uint32_t bf[4][2];
#pragma unroll
        for (int j = 0; j < 4; j++) {
            int nb = n0 + 8 * j + g;
            if (BKM) {
                bf[j][0] = Bu[(k0 + t    ) * BSTR + nb];
                bf[j][1] = Bu[(k0 + t + 4) * BSTR + nb];
            } else {
                bf[j][0] = Bu[nb * ASTR + k0 + t];
                bf[j][1] = Bu[nb * ASTR + k0 + t + 4];
            }
        }
#pragma unroll
        for (int i = 0; i < 4; i++)
#pragma unroll
            for (int j = 0; j < 4; j++)
                mma8(acc[i][j][0], acc[i][j][1], acc[i][j][2], acc[i][j][3],
                     af[i][0], af[i][1], af[i][2], af[i][3],
                     bf[j][0], bf[j][1]);
    }
}

// ---------------------------------------------------------------------------
// gml layer GEMM: Y = tf32round(X @ Wl^T + bias). W arrives pre-converted.
// ---------------------------------------------------------------------------
__global__ __launch_bounds__(256, 2)
void gemm128_tc(const float* __restrict__ X, const uint32_t* __restrict__ W,
                const float* __restrict__ bias, float* __restrict__ Y)
{
    extern __shared__ float sm[];
    const int tid  = threadIdx.x;
    const int lane = tid & 31, wid = tid >> 5;
    const int g = lane >> 2, t = lane & 3;
    const int m0 = (wid >> 2) * 64;
    const int n0 = (wid & 3) * 32;
    const long row0 = (long)blockIdx.x * 128;

    auto fill = [&](int stage, int kc) {
        float* A_s = sm + stage * STG_GEMM;
        float* B_s = A_s + TILE_F;
#pragma unroll
        for (int it = 0; it < 4; it++) {
            int v = tid + it * 256;
            int rr = v >> 3, cc = (v & 7) * 4;
            cp16(sptr(&A_s[rr * ASTR + cc]), &X[(row0 + rr) * 128 + kc + cc]);
            cp16(sptr(&B_s[rr * ASTR + cc]), &W[rr * 128 + kc + cc]);
        }
    };

    float acc[4][4][4];
#pragma unroll
    for (int i = 0; i < 4; i++)
#pragma unroll
        for (int j = 0; j < 4; j++)
#pragma unroll
            for (int q = 0; q < 4; q++) acc[i][j][q] = 0.f;

    fill(0, 0); cp_commit();
#pragma unroll
    for (int c = 0; c < 4; c++) {
        if (c + 1 < 4) { fill((c + 1) & 1, (c + 1) * 32); cp_commit(); cp_wait<1>(); }
        else           { cp_wait<0>(); }
        __syncthreads();
        const float* A_s = sm + (c & 1) * STG_GEMM;
        compute_chunk<false, true>(A_s, A_s + TILE_F, m0, n0, g, t, acc);
        __syncthreads();
    }

    uint32_t* Yu = (uint32_t*)Y;
#pragma unroll
    for (int j = 0; j < 4; j++) {
        int col = n0 + 8 * j + 2 * t;
        float bv0 = bias[col], bv1 = bias[col + 1];
#pragma unroll
        for (int i = 0; i < 4; i++) {
            long r0 = row0 + m0 + 16 * i + g;
            long r1 = r0 + 8;
            *(uint2*)&Yu[r0 * 128 + col] =
                make_uint2(f2tf(acc[i][j][0] + bv0), f2tf(acc[i][j][1] + bv1));
            *(uint2*)&Yu[r1 * 128 + col] =
                make_uint2(f2tf(acc[i][j][2] + bv0), f2tf(acc[i][j][3] + bv1));
        }
    }
}

// ---------------------------------------------------------------------------
// Xout = tf32round(relu(G0[b] @ Yin));  Yin is tf32 bits (raw B reads).
// ---------------------------------------------------------------------------
__global__ __launch_bounds__(256, 2)
void bmm_relu_tc(const float* __restrict__ G, const float* __restrict__ Yin,
                 float* __restrict__ Xout)
{
    extern __shared__ float sm[];
    const int tid  = threadIdx.x;
    const int lane = tid & 31, wid = tid >> 5;
    const int g = lane >> 2, t = lane & 3;
    const int m0 = (wid >> 2) * 64;
    const int n0 = (wid & 3) * 32;
    const int b = blockIdx.y;
    const int row0 = blockIdx.x * 128;
    const float* A  = G   + (long)b * M_ * M_;
    const float* Bm = Yin + (long)b * M_ * 128;

    auto fill = [&](int stage, int kc) {
        float* A_s = sm + stage * STG_BMM;
        float* B_s = A_s + TILE_F;
#pragma unroll
        for (int it = 0; it < 4; it++) {
            int v = tid + it * 256;
            int rr = v >> 3, cc = (v & 7) * 4;
            cp16(sptr(&A_s[rr * ASTR + cc]), &A[(row0 + rr) * 256 + kc + cc]);
            int kk = v >> 5, nn = (v & 31) * 4;
            cp16(sptr(&B_s[kk * BSTR + nn]), &Bm[(kc + kk) * 128 + nn]);
        }
    };

    float acc[4][4][4];
#pragma unroll
    for (int i = 0; i < 4; i++)
#pragma unroll
        for (int j = 0; j < 4; j++)
#pragma unroll
            for (int q = 0; q < 4; q++) acc[i][j][q] = 0.f;

    fill(0, 0); cp_commit();
    fill(1, 32); cp_commit();
    for (int c = 0; c < 8; c++) {
        if (c + 2 < 8) { fill((c + 2) % 3, (c + 2) * 32); cp_commit(); cp_wait<2>(); }
        else if (c + 1 < 8) cp_wait<1>();
        else                cp_wait<0>();
        __syncthreads();
        const float* A_s = sm + (c % 3) * STG_BMM;
        compute_chunk<true, true>(A_s, A_s + TILE_F, m0, n0, g, t, acc);
        __syncthreads();
    }

    uint32_t* O = (uint32_t*)(Xout + (long)b * M_ * 128);
#pragma unroll
    for (int j = 0; j < 4; j++) {
        int col = n0 + 8 * j + 2 * t;
#pragma unroll
        for (int i = 0; i < 4; i++) {
            int r0 = row0 + m0 + 16 * i + g;
            int r1 = r0 + 8;
            *(uint2*)&O[r0 * 128 + col] =
                make_uint2(f2tf(fmaxf(acc[i][j][0], 0.f)),
                           f2tf(fmaxf(acc[i][j][1], 0.f)));
            *(uint2*)&O[r1 * 128 + col] =
                make_uint2(f2tf(fmaxf(acc[i][j][2], 0.f)),
                           f2tf(fmaxf(acc[i][j][3], 0.f)));
        }
    }
}

// ===========================================================================
// Mega-fused trunk + head — R8 shape; H tiles hold tf32 BITS (raw frag
// reads, no cvt in hot loop); residual stream kept fp32 in registers.
// ===========================================================================
#define HTILE_F  (128*128)
#define WCHK_TF  TILE_F
#define DSMEM_TRUNK ((2*HTILE_F + 2*WCHK_TF)*4)   // 167936 B
#define NSTG 17
#define NSLOT (NSTG*4)

__global__ __launch_bounds__(256, 1)
void trunk_head_fused(const float* __restrict__ X,
    const float* __restrict__ lin0B, const float* __restrict__ rinB,
    const float* __restrict__ rb1B,  const float* __restrict__ routB,
    const float* __restrict__ f1B,   const float* __restrict__ f2W,
    const float* __restrict__ f2B,   float* __restrict__ out)
{
    extern __shared__ float sm[];
    float* H0 = sm;                        // swizzled [128][128], tf32 bits
    float* H1 = sm + HTILE_F;
    float* Wc = sm + 2 * HTILE_F;          // 2 x [128][ASTR], tf32 bits

    const int tid  = threadIdx.x;
    const int lane = tid & 31, wid = tid >> 5;
    const int g = lane >> 2, t = lane & 3;
    const int m0 = (wid >> 2) * 64;
    const int n0 = (wid & 3) * 32;
    const long row0 = (long)blockIdx.x * 128;
    const int sw = g << 2;

    const float* bp[9] = { lin0B, rinB, rb1B, nullptr, rb1B + 128, nullptr,
                           rb1B + 256, nullptr, routB };

    auto fillWchunk = [&](int buf, int slot) {
        const uint32_t* Wp = g_Wt + (4 + (slot >> 2)) * 16384;
        int kc = (slot & 3) * 32;
        float* W_s = Wc + buf * WCHK_TF;
#pragma unroll
        for (int it = 0; it < 4; it++) {
            int v = tid + it * 256;
            int rr = v >> 3, cc = (v & 7) * 4;
            cp16(sptr(&W_s[rr * ASTR + cc]), &Wp[rr * 128 + kc + cc]);
        }
    };

    // prologue: X rows (already tf32 bits) -> H0 (swizzled), W chunk 0
#pragma unroll
    for (int it = 0; it < 16; it++) {
        int v = tid + it * 256;
        int rr = v >> 5, cc = (v & 31) * 4;
        cp16(sptr(&H0[rr * 128 + (cc ^ ((rr & 7) << 2))]),
             &X[(row0 + rr) * 128 + cc]);
    }
    fillWchunk(0, 0);
    cp_commit(); cp_wait<0>(); __syncthreads();

    float psum[8];
#pragma unroll
    for (int q = 0; q < 8; q++) psum[q] = 0.f;

    float acc[4][4][4];
    float hres[4][4][4];   // fp32 residual stream (outputs of stages 1,3,5,7)

    for (int q = 0; q < NSLOT; q++) {
        const int s = q >> 2, c = q & 3;

        if (q + 1 < NSLOT) { fillWchunk((q + 1) & 1, q + 1); cp_commit(); }

        if (c == 0) {
#pragma unroll
            for (int i = 0; i < 4; i++)
#pragma unroll
                for (int j = 0; j < 4; j++)
#pragma unroll
                    for (int z = 0; z < 4; z++) acc[i][j][z] = 0.f;
        }

        const uint32_t* Hu = (const uint32_t*)(((s & 1) || s >= 9) ? H1 : H0);
        const uint32_t* Wu = (const uint32_t*)(Wc + (q & 1) * WCHK_TF);
        const int kc = c * 32;

#pragma unroll
        for (int ks = 0; ks < 4; ks++) {
            const int k0 = ks * 8;
            uint32_t af[4][4];
#pragma unroll
            for (int i = 0; i < 4; i++) {
                int r0 = m0 + 16 * i + g;    // (r&7)==g
                int r1 = r0 + 8;
                af[i][0] = Hu[r0 * 128 + ((kc + k0 + t    ) ^ sw)];
                af[i][1] = Hu[r1 * 128 + ((kc + k0 + t    ) ^ sw)];
                af[i][2] = Hu[r0 * 128 + ((kc + k0 + t + 4) ^ sw)];
                af[i][3] = Hu[r1 * 128 + ((kc + k0 + t + 4) ^ sw)];
            }
            uint32_t bf[4][2];
#pragma unroll
            for (int j = 0; j < 4; j++) {
                int nb = n0 + 8 * j + g;
                bf[j][0] = Wu[nb * ASTR + k0 + t];
                bf[j][1] = Wu[nb * ASTR + k0 + t + 4];
            }
#pragma unroll
            for (int i = 0; i < 4; i++)
#pragma unroll
                for (int j = 0; j < 4; j++)
                    mma8(acc[i][j][0], acc[i][j][1], acc[i][j][2], acc[i][j][3],
                         af[i][0], af[i][1], af[i][2], af[i][3],
                         bf[j][0], bf[j][1]);
        }

        if (c == 3) {
            if (s < 9) {
                uint32_t* D = (uint32_t*)((s & 1) ? H0 : H1);
                const bool relu = (s == 2 || s == 4 || s == 6);
                const bool res  = (s == 3 || s == 5 || s == 7);
                const bool keep = (s == 1) || res;   // residual-stream stages
                const float* bias = bp[s];
#pragma unroll
                for (int j = 0; j < 4; j++) {
                    int col = n0 + 8 * j + 2 * t;
                    float bv0 = bias ? bias[col]     : 0.f;
                    float bv1 = bias ? bias[col + 1] : 0.f;
#pragma unroll
                    for (int i = 0; i < 4; i++) {
                        int r0 = m0 + 16 * i + g;   // (r&7)==g
                        int r1 = r0 + 8;
                        int p0 = r0 * 128 + (col ^ sw);
                        int p1 = r1 * 128 + (col ^ sw);
                        float v00 = acc[i][j][0] + bv0, v01 = acc[i][j][1] + bv1;
                        float v10 = acc[i][j][2] + bv0, v11 = acc[i][j][3] + bv1;
                        if (relu) { v00 = fmaxf(v00, 0.f); v01 = fmaxf(v01, 0.f);
                                    v10 = fmaxf(v10, 0.f); v11 = fmaxf(v11, 0.f); }
                        if (res) {
                            v00 += hres[i][j][0]; v01 += hres[i][j][1];
                            v10 += hres[i][j][2]; v11 += hres[i][j][3];
                        }
                        if (keep) {
                            hres[i][j][0] = v00; hres[i][j][1] = v01;
                            hres[i][j][2] = v10; hres[i][j][3] = v11;
                        }
                        *(uint2*)&D[p0] = make_uint2(f2tf(v00), f2tf(v01));
                        *(uint2*)&D[p1] = make_uint2(f2tf(v10), f2tf(v11));
                    }
                }
            } else {
                int ncb = (s - 9) * 128;
#pragma unroll
                for (int j = 0; j < 4; j++) {
                    int col = ncb + n0 + 8 * j + 2 * t;
                    float bb0 = f1B[col], bb1 = f1B[col + 1];
                    float s0  = f2W[col], s1  = f2W[col + 1];
#pragma unroll
                    for (int i = 0; i < 4; i++) {
                        psum[2*i]   += fmaxf(acc[i][j][0] + bb0, 0.f) * s0
                                     + fmaxf(acc[i][j][1] + bb1, 0.f) * s1;
                        psum[2*i+1] += fmaxf(acc[i][j][2] + bb0, 0.f) * s0
                                     + fmaxf(acc[i][j][3] + bb1, 0.f) * s1;
                    }
                }
            }
        }

        if (q + 1 < NSLOT) cp_wait<0>();
        __syncthreads();
    }

    // reduce 16 partials per row; overlay scratch on weight buffers
    float (*red)[17] = (float(*)[17])Wc;
    const int qn = (wid & 3) * 4 + t;
#pragma unroll
    for (int i = 0; i < 4; i++) {
        red[m0 + 16 * i + g    ][qn] = psum[2*i];
        red[m0 + 16 * i + g + 8][qn] = psum[2*i+1];
    }
    __syncthreads();
    if (tid < 128) {
        float sum = f2B[0];
#pragma unroll
        for (int k = 0; k < 16; k++) sum += red[tid][k];
        out[row0 + tid] = sum;
    }
}

// ---------------------------------------------------------------------------
extern "C" void kernel_launch(void* const* d_in, const int* in_sizes, int n_in,
                              void* d_out, int out_size)
{
    const float* G     = (const float*)d_in[0];
    const float* xG    = (const float*)d_in[1];
    const float* gmlW  = (const float*)d_in[2];
    const float* gmlB  = (const float*)d_in[3];
    const float* lin0W = (const float*)d_in[4];
    const float* lin0B = (const float*)d_in[5];
    const float* rinW  = (const float*)d_in[6];
    const float* rinB  = (const float*)d_in[7];
    const float* rb1W  = (const float*)d_in[8];
    const float* rb1B  = (const float*)d_in[9];
    const float* rb2W  = (const float*)d_in[10];
    const float* routW = (const float*)d_in[11];
    const float* routB = (const float*)d_in[12];
    const float* f1W   = (const float*)d_in[13];
    const float* f1B   = (const float*)d_in[14];
    const float* f2W   = (const float*)d_in[15];
    const float* f2B   = (const float*)d_in[16];
    float* out = (float*)d_out;

    float *bY, *bX;
    uint32_t* wt;
    cudaGetSymbolAddress((void**)&bY, g_Y);
    cudaGetSymbolAddress((void**)&bX, g_X);
    cudaGetSymbolAddress((void**)&wt, g_Wt);

    cudaFuncSetAttribute(gemm128_tc,
                         cudaFuncAttributeMaxDynamicSharedMemorySize, DSMEM_GEMM);
    cudaFuncSetAttribute(bmm_relu_tc,
                         cudaFuncAttributeMaxDynamicSharedMemorySize, DSMEM_BMM3);
    cudaFuncSetAttribute(trunk_head_fused,
                         cudaFuncAttributeMaxDynamicSharedMemorySize, DSMEM_TRUNK);

    // pre-convert all weights to tf32 bits (bit-identical to per-read cvt)
    convert_weights<<<(NWT + 255) / 256, 256>>>(gmlW, lin0W, rinW, rb1W,
                                                rb2W, routW, f1W);

    const int GB = BM_ / 128;   // 1024 blocks
    dim3 blk(256);

    // GNN message-passing layers
    const float* xcur = xG;
    for (int l = 0; l < NGL; l++) {
        gemm128_tc<<<GB, blk, DSMEM_GEMM>>>(xcur, wt + (long)l * 16384,
                                            gmlB + l * 128, bY);
        bmm_relu_tc<<<dim3(2, B_), blk, DSMEM_BMM3>>>(G, bY, bX);
        xcur = bX;
    }

    // Fused MLP trunk + head (weights from pre-converted table)
    trunk_head_fused<<<GB, blk, DSMEM_TRUNK>>>(bX,
        lin0B, rinB, rb1B, routB, f1B, f2W, f2B, out);
}

// round 15
// speedup vs baseline: 1.3192x; 1.1061x over previous
#include <cuda_runtime.h>
#include <cstdint>

#define B_   512
#define M_   256
#define BM_  (B_*M_)      // 131072 rows
#define NGL  4

// Scratch (allocation-free rule: __device__ globals)
__device__ float g_Y[BM_*128];
__device__ float g_X[BM_*128];
// pre-converted tf32 weight bits: gml stages 0..3, then trunk stages 0..16
#define NWT (21*16384)
__device__ uint32_t g_Wt[NWT];

// ---------------------------------------------------------------------------
// helpers
// ---------------------------------------------------------------------------
__device__ __forceinline__ uint32_t f2tf(float x) {
    uint32_t r;
    asm("cvt.rna.tf32.f32 %0, %1;" : "=r"(r) : "f"(x));
    return r;
}

__device__ __forceinline__ void mma8(float& c0, float& c1, float& c2, float& c3,
                                     uint32_t a0, uint32_t a1, uint32_t a2, uint32_t a3,
                                     uint32_t b0, uint32_t b1)
{
    asm volatile(
        "mma.sync.aligned.m16n8k8.row.col.f32.tf32.tf32.f32 "
        "{%0,%1,%2,%3}, {%4,%5,%6,%7}, {%8,%9}, {%0,%1,%2,%3};"
        : "+f"(c0), "+f"(c1), "+f"(c2), "+f"(c3)
        : "r"(a0), "r"(a1), "r"(a2), "r"(a3), "r"(b0), "r"(b1));
}

__device__ __forceinline__ uint32_t sptr(const void* p) {
    return (uint32_t)__cvta_generic_to_shared(p);
}
__device__ __forceinline__ void cp16(uint32_t s, const void* g) {
    asm volatile("cp.async.cg.shared.global [%0], [%1], 16;" :: "r"(s), "l"(g));
}
__device__ __forceinline__ void cp_commit() {
    asm volatile("cp.async.commit_group;");
}
template<int N> __device__ __forceinline__ void cp_wait() {
    asm volatile("cp.async.wait_group %0;" :: "n"(N));
}

#define ASTR 36
#define BSTR 136
#define TILE_F   (128*ASTR)
#define STG_GEMM (TILE_F*2)
#define STG_BMM  (TILE_F + 32*BSTR)
#define DSMEM_GEMM  (STG_GEMM*2*4)
#define DSMEM_BMM3  (STG_BMM*3*4)

// ---------------------------------------------------------------------------
// weight pre-convert: fp32 -> tf32 bits
// ---------------------------------------------------------------------------
__global__ void convert_weights(const float* __restrict__ gmlW,
                                const float* __restrict__ lin0W,
                                const float* __restrict__ rinW,
                                const float* __restrict__ rb1W,
                                const float* __restrict__ rb2W,
                                const float* __restrict__ routW,
                                const float* __restrict__ f1W)
{
    int idx = blockIdx.x * 256 + threadIdx.x;
    if (idx >= NWT) return;
    float v;
    if (idx < 4 * 16384) {
        v = gmlW[idx];
    } else {
        int j = idx - 4 * 16384;
        int s = j >> 14, off = j & 16383;
        switch (s) {
            case 0: v = lin0W[off]; break;
            case 1: v = rinW[off]; break;
            case 2: v = rb1W[off]; break;
            case 3: v = rb2W[off]; break;
            case 4: v = rb1W[16384 + off]; break;
            case 5: v = rb2W[16384 + off]; break;
            case 6: v = rb1W[32768 + off]; break;
            case 7: v = rb2W[32768 + off]; break;
            case 8: v = routW[off]; break;
            default: v = f1W[(s - 9) * 16384 + off]; break;
        }
    }
    g_Wt[idx] = f2tf(v);
}

// ---------------------------------------------------------------------------
// warp-tile compute over one 32-k chunk. ACVT: cvt on A-side (fp32 in smem);
// B-side raw tf32 bits.
// ---------------------------------------------------------------------------
template<bool BKM, bool ACVT>
__device__ __forceinline__ void compute_chunk(const float* __restrict__ A_s,
                                              const float* __restrict__ B_s,
                                              int m0, int n0, int g, int t,
                                              float acc[4][4][4])
{
    const uint32_t* Au = (const uint32_t*)A_s;
    const uint32_t* Bu = (const uint32_t*)B_s;
#pragma unroll
    for (int ks = 0; ks < 4; ks++) {
        const int k0 = ks * 8;
        uint32_t af[4][4];
#pragma unroll
        for (int i = 0; i < 4; i++) {
            int mr = m0 + 16 * i;
            if (ACVT) {
                af[i][0] = f2tf(A_s[(mr + g    ) * ASTR + k0 + t]);
                af[i][1] = f2tf(A_s[(mr + g + 8) * ASTR + k0 + t]);
                af[i][2] = f2tf(A_s[(mr + g    ) * ASTR + k0 + t + 4]);
                af[i][3] = f2tf(A_s[(mr + g + 8) * ASTR + k0 + t + 4]);
            } else {
                af[i][0] = Au[(mr + g    ) * ASTR + k0 + t];
                af[i][1] = Au[(mr + g + 8) * ASTR + k0 + t];
                af[i][2] = Au[(mr + g    ) * ASTR + k0 + t + 4];
                af[i][3] = Au[(mr + g + 8) * ASTR + k0 + t + 4];
            }
        }
        uint32_t bf[4][2];
#pragma unroll
        for (int j = 0; j < 4; j++) {
            int nb = n0 + 8 * j + g;
            if (BKM) {
                bf[j][0] = Bu[(k0 + t    ) * BSTR + nb];
                bf[j][1] = Bu[(k0 + t + 4) * BSTR + nb];
            } else {
                bf[j][0] = Bu[nb * ASTR + k0 + t];
                bf[j][1] = Bu[nb * ASTR + k0 + t + 4];
            }
        }
#pragma unroll
        for (int i = 0; i < 4; i++)
#pragma unroll
            for (int j = 0; j < 4; j++)
                mma8(acc[i][j][0], acc[i][j][1], acc[i][j][2], acc[i][j][3],
                     af[i][0], af[i][1], af[i][2], af[i][3],
                     bf[j][0], bf[j][1]);
    }
}

// ---------------------------------------------------------------------------
// gml layer GEMM: Y = tf32round(X @ Wl^T + bias). W pre-converted. (R13)
// ---------------------------------------------------------------------------
__global__ __launch_bounds__(256, 2)
void gemm128_tc(const float* __restrict__ X, const uint32_t* __restrict__ W,
                const float* __restrict__ bias, float* __restrict__ Y)
{
    extern __shared__ float sm[];
    const int tid  = threadIdx.x;
    const int lane = tid & 31, wid = tid >> 5;
    const int g = lane >> 2, t = lane & 3;
    const int m0 = (wid >> 2) * 64;
    const int n0 = (wid & 3) * 32;
    const long row0 = (long)blockIdx.x * 128;

    auto fill = [&](int stage, int kc) {
        float* A_s = sm + stage * STG_GEMM;
        float* B_s = A_s + TILE_F;
#pragma unroll
        for (int it = 0; it < 4; it++) {
            int v = tid + it * 256;
            int rr = v >> 3, cc = (v & 7) * 4;
            cp16(sptr(&A_s[rr * ASTR + cc]), &X[(row0 + rr) * 128 + kc + cc]);
            cp16(sptr(&B_s[rr * ASTR + cc]), &W[rr * 128 + kc + cc]);
        }
    };

    float acc[4][4][4];
#pragma unroll
    for (int i = 0; i < 4; i++)
#pragma unroll
        for (int j = 0; j < 4; j++)
#pragma unroll
            for (int q = 0; q < 4; q++) acc[i][j][q] = 0.f;

    fill(0, 0); cp_commit();
#pragma unroll
    for (int c = 0; c < 4; c++) {
        if (c + 1 < 4) { fill((c + 1) & 1, (c + 1) * 32); cp_commit(); cp_wait<1>(); }
        else           { cp_wait<0>(); }
        __syncthreads();
        const float* A_s = sm + (c & 1) * STG_GEMM;
        compute_chunk<false, true>(A_s, A_s + TILE_F, m0, n0, g, t, acc);
        __syncthreads();
    }

    uint32_t* Yu = (uint32_t*)Y;
#pragma unroll
    for (int j = 0; j < 4; j++) {
        int col = n0 + 8 * j + 2 * t;
        float bv0 = bias[col], bv1 = bias[col + 1];
#pragma unroll
        for (int i = 0; i < 4; i++) {
            long r0 = row0 + m0 + 16 * i + g;
            long r1 = r0 + 8;
            *(uint2*)&Yu[r0 * 128 + col] =
                make_uint2(f2tf(acc[i][j][0] + bv0), f2tf(acc[i][j][1] + bv1));
            *(uint2*)&Yu[r1 * 128 + col] =
                make_uint2(f2tf(acc[i][j][2] + bv0), f2tf(acc[i][j][3] + bv1));
        }
    }
}

// ---------------------------------------------------------------------------
// Xout = tf32round(relu(G0[b] @ Yin));  Yin tf32 bits, 3-stage ring. (R13)
// ---------------------------------------------------------------------------
__global__ __launch_bounds__(256, 2)
void bmm_relu_tc(const float* __restrict__ G, const float* __restrict__ Yin,
                 float* __restrict__ Xout)
{
    extern __shared__ float sm[];
    const int tid  = threadIdx.x;
    const int lane = tid & 31, wid = tid >> 5;
    const int g = lane >> 2, t = lane & 3;
    const int m0 = (wid >> 2) * 64;
    const int n0 = (wid & 3) * 32;
    const int b = blockIdx.y;
    const int row0 = blockIdx.x * 128;
    const float* A  = G   + (long)b * M_ * M_;
    const float* Bm = Yin + (long)b * M_ * 128;

    auto fill = [&](int stage, int kc) {
        float* A_s = sm + stage * STG_BMM;
        float* B_s = A_s + TILE_F;
#pragma unroll
        for (int it = 0; it < 4; it++) {
            int v = tid + it * 256;
            int rr = v >> 3, cc = (v & 7) * 4;
            cp16(sptr(&A_s[rr * ASTR + cc]), &A[(row0 + rr) * 256 + kc + cc]);
            int kk = v >> 5, nn = (v & 31) * 4;
            cp16(sptr(&B_s[kk * BSTR + nn]), &Bm[(kc + kk) * 128 + nn]);
        }
    };

    float acc[4][4][4];
#pragma unroll
    for (int i = 0; i < 4; i++)
#pragma unroll
        for (int j = 0; j < 4; j++)
#pragma unroll
            for (int q = 0; q < 4; q++) acc[i][j][q] = 0.f;

    fill(0, 0); cp_commit();
    fill(1, 32); cp_commit();
    for (int c = 0; c < 8; c++) {
        if (c + 2 < 8) { fill((c + 2) % 3, (c + 2) * 32); cp_commit(); cp_wait<2>(); }
        else if (c + 1 < 8) cp_wait<1>();
        else                cp_wait<0>();
        __syncthreads();
        const float* A_s = sm + (c % 3) * STG_BMM;
        compute_chunk<true, true>(A_s, A_s + TILE_F, m0, n0, g, t, acc);
        __syncthreads();
    }

    uint32_t* O = (uint32_t*)(Xout + (long)b * M_ * 128);
#pragma unroll
    for (int j = 0; j < 4; j++) {
        int col = n0 + 8 * j + 2 * t;
#pragma unroll
        for (int i = 0; i < 4; i++) {
            int r0 = row0 + m0 + 16 * i + g;
            int r1 = r0 + 8;
            *(uint2*)&O[r0 * 128 + col] =
                make_uint2(f2tf(fmaxf(acc[i][j][0], 0.f)),
                           f2tf(fmaxf(acc[i][j][1], 0.f)));
            *(uint2*)&O[r1 * 128 + col] =
                make_uint2(f2tf(fmaxf(acc[i][j][2], 0.f)),
                           f2tf(fmaxf(acc[i][j][3], 0.f)));
        }
    }
}

// ===========================================================================
// Mega-fused trunk + head — full-tile single-buffered weights: per stage the
// whole K=128 runs barrier-free from stable H + Ws tiles; W(s+1) streams in
// after one sync, overlapped with the epilogue. 34 barriers total (vs 136).
// H/Ws layout: swizzled [128][128] tf32 bits, word = r*128 + (c ^ ((r&7)<<2)).
// ===========================================================================
#define HTILE_F  (128*128)
#define DSMEM_TRUNK (3*HTILE_F*4)   // H0 + H1 + Ws = 196608 B
#define NSTG 17

__global__ __launch_bounds__(256, 1)
void trunk_head_fused(const float* __restrict__ X,
    const float* __restrict__ lin0B, const float* __restrict__ rinB,
    const float* __restrict__ rb1B,  const float* __restrict__ routB,
    const float* __restrict__ f1B,   const float* __restrict__ f2W,
    const float* __restrict__ f2B,   float* __restrict__ out)
{
    extern __shared__ float sm[];
    float* H0 = sm;
    float* H1 = sm + HTILE_F;
    float* Ws = sm + 2 * HTILE_F;

    const int tid  = threadIdx.x;
    const int lane = tid & 31, wid = tid >> 5;
    const int g = lane >> 2, t = lane & 3;
    const int m0 = (wid >> 2) * 64;
    const int n0 = (wid & 3) * 32;
    const long row0 = (long)blockIdx.x * 128;
    const int sw = g << 2;

    const float* bp[9] = { lin0B, rinB, rb1B, nullptr, rb1B + 128, nullptr,
                           rb1B + 256, nullptr, routB };

    // full 128x128 weight tile -> Ws (swizzled), 16 cp16 per thread
    auto fillW = [&](int s) {
        const uint32_t* Wp = g_Wt + (4 + s) * 16384;
#pragma unroll
        for (int it = 0; it < 16; it++) {
            int v = tid + it * 256;
            int rr = v >> 5, cc = (v & 31) * 4;
            cp16(sptr(&Ws[rr * 128 + (cc ^ ((rr & 7) << 2))]),
                 &Wp[rr * 128 + cc]);
        }
    };

    // prologue: X rows (tf32 bits already? no — X here is bmm output, tf32
    // bits stored as float) -> H0 swizzled; weight tile 0 -> Ws
#pragma unroll
    for (int it = 0; it < 16; it++) {
        int v = tid + it * 256;
        int rr = v >> 5, cc = (v & 31) * 4;
        cp16(sptr(&H0[rr * 128 + (cc ^ ((rr & 7) << 2))]),
             &X[(row0 + rr) * 128 + cc]);
    }
    fillW(0);
    cp_commit(); cp_wait<0>(); __syncthreads();

    float psum[8];
#pragma unroll
    for (int q = 0; q < 8; q++) psum[q] = 0.f;

    float acc[4][4][4];
    float hres[4][4][4];   // fp32 residual stream (outputs of stages 1,3,5,7)

    for (int s = 0; s < NSTG; s++) {
#pragma unroll
        for (int i = 0; i < 4; i++)
#pragma unroll
            for (int j = 0; j < 4; j++)
#pragma unroll
                for (int z = 0; z < 4; z++) acc[i][j][z] = 0.f;

        const uint32_t* Hu = (const uint32_t*)(((s & 1) || s >= 9) ? H1 : H0);
        const uint32_t* Wu = (const uint32_t*)Ws;

        // full K=128, no intra-stage barriers (H and Ws stable)
#pragma unroll
        for (int ks = 0; ks < 16; ks++) {
            const int k0 = ks * 8;
            uint32_t af[4][4];
#pragma unroll
            for (int i = 0; i < 4; i++) {
                int r0 = m0 + 16 * i + g;    // (r&7)==g
                int r1 = r0 + 8;
                af[i][0] = Hu[r0 * 128 + ((k0 + t    ) ^ sw)];
                af[i][1] = Hu[r1 * 128 + ((k0 + t    ) ^ sw)];
                af[i][2] = Hu[r0 * 128 + ((k0 + t + 4) ^ sw)];
                af[i][3] = Hu[r1 * 128 + ((k0 + t + 4) ^ sw)];
            }
            uint32_t bf[4][2];
#pragma unroll
            for (int j = 0; j < 4; j++) {
                int nb = n0 + 8 * j + g;     // (nb&7)==g
                bf[j][0] = Wu[nb * 128 + ((k0 + t    ) ^ sw)];
                bf[j][1] = Wu[nb * 128 + ((k0 + t + 4) ^ sw)];
            }
#pragma unroll
            for (int i = 0; i < 4; i++)
#pragma unroll
                for (int j = 0; j < 4; j++)
                    mma8(acc[i][j][0], acc[i][j][1], acc[i][j][2], acc[i][j][3],
                         af[i][0], af[i][1], af[i][2], af[i][3],
                         bf[j][0], bf[j][1]);
        }

        __syncthreads();                       // all Ws reads complete
        if (s + 1 < NSTG) { fillW(s + 1); cp_commit(); }

        if (s < 9) {
            uint32_t* D = (uint32_t*)((s & 1) ? H0 : H1);
            const bool relu = (s == 2 || s == 4 || s == 6);
            const bool res  = (s == 3 || s == 5 || s == 7);
            const bool keep = (s == 1) || res;
            const float* bias = bp[s];
#pragma unroll
            for (int j = 0; j < 4; j++) {
                int col = n0 + 8 * j + 2 * t;
                float bv0 = bias ? bias[col]     : 0.f;
                float bv1 = bias ? bias[col + 1] : 0.f;
#pragma unroll
                for (int i = 0; i < 4; i++) {
                    int r0 = m0 + 16 * i + g;
                    int r1 = r0 + 8;
                    int p0 = r0 * 128 + (col ^ sw);
                    int p1 = r1 * 128 + (col ^ sw);
                    float v00 = acc[i][j][0] + bv0, v01 = acc[i][j][1] + bv1;
                    float v10 = acc[i][j][2] + bv0, v11 = acc[i][j][3] + bv1;
                    if (relu) { v00 = fmaxf(v00, 0.f); v01 = fmaxf(v01, 0.f);
                                v10 = fmaxf(v10, 0.f); v11 = fmaxf(v11, 0.f); }
                    if (res) {
                        v00 += hres[i][j][0]; v01 += hres[i][j][1];
                        v10 += hres[i][j][2]; v11 += hres[i][j][3];
                    }
                    if (keep) {
                        hres[i][j][0] = v00; hres[i][j][1] = v01;
                        hres[i][j][2] = v10; hres[i][j][3] = v11;
                    }
                    *(uint2*)&D[p0] = make_uint2(f2tf(v00), f2tf(v01));
                    *(uint2*)&D[p1] = make_uint2(f2tf(v10), f2tf(v11));
                }
            }
        } else {
            int ncb = (s - 9) * 128;
#pragma unroll
            for (int j = 0; j < 4; j++) {
                int col = ncb + n0 + 8 * j + 2 * t;
                float bb0 = f1B[col], bb1 = f1B[col + 1];
                float s0  = f2W[col], s1  = f2W[col + 1];
#pragma unroll
                for (int i = 0; i < 4; i++) {
                    psum[2*i]   += fmaxf(acc[i][j][0] + bb0, 0.f) * s0
                                 + fmaxf(acc[i][j][1] + bb1, 0.f) * s1;
                    psum[2*i+1] += fmaxf(acc[i][j][2] + bb0, 0.f) * s0
                                 + fmaxf(acc[i][j][3] + bb1, 0.f) * s1;
                }
            }
        }

        if (s + 1 < NSTG) cp_wait<0>();
        __syncthreads();
    }

    // reduce 16 partials per row; overlay scratch on Ws
    float (*red)[17] = (float(*)[17])Ws;
    const int qn = (wid & 3) * 4 + t;
#pragma unroll
    for (int i = 0; i < 4; i++) {
        red[m0 + 16 * i + g    ][qn] = psum[2*i];
        red[m0 + 16 * i + g + 8][qn] = psum[2*i+1];
    }
    __syncthreads();
    if (tid < 128) {
        float sum = f2B[0];
#pragma unroll
        for (int k = 0; k < 16; k++) sum += red[tid][k];
        out[row0 + tid] = sum;
    }
}

// ---------------------------------------------------------------------------
extern "C" void kernel_launch(void* const* d_in, const int* in_sizes, int n_in,
                              void* d_out, int out_size)
{
    const float* G     = (const float*)d_in[0];
    const float* xG    = (const float*)d_in[1];
    const float* gmlW  = (const float*)d_in[2];
    const float* gmlB  = (const float*)d_in[3];
    const float* lin0W = (const float*)d_in[4];
    const float* lin0B = (const float*)d_in[5];
    const float* rinW  = (const float*)d_in[6];
    const float* rinB  = (const float*)d_in[7];
    const float* rb1W  = (const float*)d_in[8];
    const float* rb1B  = (const float*)d_in[9];
    const float* rb2W  = (const float*)d_in[10];
    const float* routW = (const float*)d_in[11];
    const float* routB = (const float*)d_in[12];
    const float* f1W   = (const float*)d_in[13];
    const float* f1B   = (const float*)d_in[14];
    const float* f2W   = (const float*)d_in[15];
    const float* f2B   = (const float*)d_in[16];
    float* out = (float*)d_out;

    float *bY, *bX;
    uint32_t* wt;
    cudaGetSymbolAddress((void**)&bY, g_Y);
    cudaGetSymbolAddress((void**)&bX, g_X);
    cudaGetSymbolAddress((void**)&wt, g_Wt);

    cudaFuncSetAttribute(gemm128_tc,
                         cudaFuncAttributeMaxDynamicSharedMemorySize, DSMEM_GEMM);
    cudaFuncSetAttribute(bmm_relu_tc,
                         cudaFuncAttributeMaxDynamicSharedMemorySize, DSMEM_BMM3);
    cudaFuncSetAttribute(trunk_head_fused,
                         cudaFuncAttributeMaxDynamicSharedMemorySize, DSMEM_TRUNK);

    // pre-convert all weights to tf32 bits
    convert_weights<<<(NWT + 255) / 256, 256>>>(gmlW, lin0W, rinW, rb1W,
                                                rb2W, routW, f1W);

    const int GB = BM_ / 128;   // 1024 blocks
    dim3 blk(256);

    // GNN message-passing layers
    const float* xcur = xG;
    for (int l = 0; l < NGL; l++) {
        gemm128_tc<<<GB, blk, DSMEM_GEMM>>>(xcur, wt + (long)l * 16384,
                                            gmlB + l * 128, bY);
        bmm_relu_tc<<<dim3(2, B_), blk, DSMEM_BMM3>>>(G, bY, bX);
        xcur = bX;
    }

    // Fused MLP trunk + head (full-tile weight streaming, 34 barriers)
    trunk_head_fused<<<GB, blk, DSMEM_TRUNK>>>(bX,
        lin0B, rinB, rb1B, routB, f1B, f2W, f2B, out);
}